// round 5
// baseline (speedup 1.0000x reference)
#include <cuda_runtime.h>
#include <math.h>

#define BB 8
#define CC 64
#define NN 2048
#define KK 32
#define BN (BB*NN)   // 16384 points

// ---------------- device scratch (no allocations allowed) ----------------
__device__ float g_xx[BN];
__device__ int   g_idx[BN*KK];
__device__ float g_WT [3*CC*CC];   // Wq/Wk/Wv transposed: [w][cin][cout]
__device__ float g_W1T[CC*128];    // [cin][cout]
__device__ float g_W2T[128*CC];    // [cin][cout]
__device__ float g_q [BN*CC];      // point-major [bn][c]
__device__ float g_yk[BN*CC];
__device__ float g_yv[BN*CC];
__device__ float g_s1[BN*CC];      // x + attn_out (pre-BN1), point-major
__device__ float g_x1[BN*CC];      // BN1 output, point-major
__device__ float g_h [BN*128];     // lrelu(W1@x1), point-major
__device__ float g_s2[BN*CC];      // x1 + ff (pre-BN2), point-major
__device__ float g_mean1[CC], g_rstd1[CC], g_mean2[CC], g_rstd2[CC];

// ---------------- 0) transpose weights ----------------
__global__ void k_prep(const float* __restrict__ Wq, const float* __restrict__ Wk,
                       const float* __restrict__ Wv, const float* __restrict__ W1,
                       const float* __restrict__ W2) {
    int i = blockIdx.x * 256 + threadIdx.x;
    if (i < CC*CC) {
        int o = i >> 6, ci = i & 63;
        g_WT[0*CC*CC + ci*CC + o] = Wq[i];
        g_WT[1*CC*CC + ci*CC + o] = Wk[i];
        g_WT[2*CC*CC + ci*CC + o] = Wv[i];
    }
    if (i < 128*CC) {
        int o = i >> 6, ci = i & 63;      // W1[o][ci], o<128
        g_W1T[ci*128 + o] = W1[i];
        int co = i >> 7, k2 = i & 127;    // W2[co][k2], co<64
        g_W2T[k2*CC + co] = W2[i];
    }
}

// ---------------- 1) per-point squared norms ----------------
__global__ void k_xx(const float* __restrict__ x) {
    int b = blockIdx.y;
    int n = blockIdx.x * 256 + threadIdx.x;
    const float* xb = x + b*CC*NN;
    float s = 0.f;
#pragma unroll
    for (int c = 0; c < CC; c++) { float v = xb[c*NN + n]; s = fmaf(v, v, s); }
    g_xx[b*NN + n] = s;
}

// ---------------- 2) KNN: top-32 largest neg_sq_dist ----------------
// thread-per-query; query in registers; candidate tile broadcast from smem;
// top-k kept ASCENDING in registers via fully unrolled sorted-insert.
__global__ void k_knn(const float* __restrict__ x) {
    __shared__ float shc[CC*64];   // [c][m]
    __shared__ float shxx[64];
    int b = blockIdx.y;
    int n = blockIdx.x * 64 + threadIdx.x;
    const float* xb = x + b*CC*NN;

    float q[CC];
#pragma unroll
    for (int c = 0; c < CC; c++) q[c] = xb[c*NN + n];
    float xxn = g_xx[b*NN + n];

    float bv[KK]; int bi[KK];
#pragma unroll
    for (int i = 0; i < KK; i++) { bv[i] = -3.4e38f; bi[i] = 0; }

    for (int t = 0; t < NN/64; t++) {
        int m0 = t * 64;
        __syncthreads();
        for (int i = threadIdx.x; i < CC*64; i += 64) {
            int c = i >> 6, m = i & 63;
            shc[c*64 + m] = xb[c*NN + m0 + m];
        }
        shxx[threadIdx.x] = g_xx[b*NN + m0 + threadIdx.x];
        __syncthreads();

#pragma unroll 1
        for (int m4 = 0; m4 < 16; m4++) {
            float a0 = 0.f, a1 = 0.f, a2 = 0.f, a3 = 0.f;
#pragma unroll
            for (int c = 0; c < CC; c++) {
                float4 s = *(const float4*)&shc[c*64 + m4*4];
                a0 = fmaf(q[c], s.x, a0);
                a1 = fmaf(q[c], s.y, a1);
                a2 = fmaf(q[c], s.z, a2);
                a3 = fmaf(q[c], s.w, a3);
            }
            int mb = m0 + m4*4;
            float vals[4];
            vals[0] = 2.f*a0 - xxn - shxx[m4*4 + 0];
            vals[1] = 2.f*a1 - xxn - shxx[m4*4 + 1];
            vals[2] = 2.f*a2 - xxn - shxx[m4*4 + 2];
            vals[3] = 2.f*a3 - xxn - shxx[m4*4 + 3];
#pragma unroll
            for (int u = 0; u < 4; u++) {
                float val = vals[u];
                int   mi  = mb + u;
                if (val > bv[0]) {
                    bool p_prev = true;
#pragma unroll
                    for (int i = 0; i < KK; i++) {
                        bool p = (i < KK-1) ? (val > bv[i+1]) : false;
                        float nv = p ? bv[i+1] : (p_prev ? val : bv[i]);
                        int   ni = p ? bi[i+1] : (p_prev ? mi  : bi[i]);
                        bv[i] = nv; bi[i] = ni;
                        p_prev = p;
                    }
                }
            }
        }
    }
    int* op = g_idx + (b*NN + n)*KK;
#pragma unroll
    for (int i = 0; i < KK; i++) op[i] = bi[i];
}

// ---------------- 3) projections q/yk/yv = W @ x (point-major out) ----------------
__global__ void k_proj(const float* __restrict__ x) {
    __shared__ float shx[CC*64];   // [c][p]
    __shared__ float shW[CC*CC];   // [cin][cout]
    int b  = blockIdx.y;
    int n0 = blockIdx.x * 64;
    int tid = threadIdx.x;
    const float* xb = x + b*CC*NN;
    for (int i = tid; i < CC*64; i += 256) {
        int c = i >> 6, p = i & 63;
        shx[c*64 + p] = xb[c*NN + n0 + p];
    }
    int p  = tid & 63;
    int cg = (tid >> 6) << 4;           // 16 output channels per thread
    int bn = b*NN + n0 + p;
    for (int w = 0; w < 3; w++) {
        __syncthreads();
        for (int i = tid; i < CC*CC; i += 256) shW[i] = g_WT[w*CC*CC + i];
        __syncthreads();
        float4 acc[4];
#pragma unroll
        for (int g = 0; g < 4; g++) acc[g] = make_float4(0.f, 0.f, 0.f, 0.f);
#pragma unroll
        for (int k = 0; k < CC; k++) {
            float xv = shx[k*64 + p];
#pragma unroll
            for (int g = 0; g < 4; g++) {
                float4 wv = *(const float4*)&shW[k*CC + cg + g*4];
                acc[g].x = fmaf(xv, wv.x, acc[g].x);
                acc[g].y = fmaf(xv, wv.y, acc[g].y);
                acc[g].z = fmaf(xv, wv.z, acc[g].z);
                acc[g].w = fmaf(xv, wv.w, acc[g].w);
            }
        }
        float* dst = (w == 0 ? g_q : (w == 1 ? g_yk : g_yv)) + bn*CC + cg;
#pragma unroll
        for (int g = 0; g < 4; g++) *(float4*)&dst[g*4] = acc[g];
    }
}

// ---------------- 4) attention (warp per point) + residual -> s1 ----------------
__global__ void k_attn(const float* __restrict__ x) {
    __shared__ float qsh[8][64];
    __shared__ float ykn[8][64];
    __shared__ float att[8][KK*8];
    __shared__ int   nid[8][KK];
    int tid  = threadIdx.x;
    int wid  = tid >> 5, lane = tid & 31;
    int bn   = blockIdx.x * 8 + wid;
    int b    = bn >> 11;
    int n    = bn & (NN - 1);

    qsh[wid][lane]      = g_q [bn*CC + lane];
    qsh[wid][lane + 32] = g_q [bn*CC + lane + 32];
    ykn[wid][lane]      = g_yk[bn*CC + lane];
    ykn[wid][lane + 32] = g_yk[bn*CC + lane + 32];
    int gn = b*NN + g_idx[bn*KK + lane];   // global row of this lane's neighbor
    nid[wid][lane] = gn;
    __syncwarp();

    const float4* kr = (const float4*)&g_yk[gn*CC];
    float e[8];
#pragma unroll
    for (int h = 0; h < 8; h++) e[h] = 0.f;
#pragma unroll
    for (int c4 = 0; c4 < 16; c4++) {
        float4 kv = kr[c4];
        int c = c4*4, h = c4 >> 1;
        float t = (kv.x - ykn[wid][c+0]) * qsh[wid][c+0];
        t = fmaf(kv.y - ykn[wid][c+1], qsh[wid][c+1], t);
        t = fmaf(kv.z - ykn[wid][c+2], qsh[wid][c+2], t);
        t = fmaf(kv.w - ykn[wid][c+3], qsh[wid][c+3], t);
        e[h] += t;
    }
    const float sc = 0.3535533905932738f;  // 1/sqrt(8)
#pragma unroll
    for (int h = 0; h < 8; h++) {
        float eh = e[h] * sc;
        float mx = eh;
#pragma unroll
        for (int o = 16; o > 0; o >>= 1) mx = fmaxf(mx, __shfl_xor_sync(0xffffffffu, mx, o));
        float ex = __expf(eh - mx);
        float sm = ex;
#pragma unroll
        for (int o = 16; o > 0; o >>= 1) sm += __shfl_xor_sync(0xffffffffu, sm, o);
        att[wid][lane*8 + h] = ex / sm;
    }
    __syncwarp();

    // out[c] = sum_j a[j][c>>3]*yv_j[c] - yv_center[c]  (softmax sums to 1)
    float acc0 = 0.f, acc1 = 0.f;
    int h0 = lane >> 3, h1 = (lane >> 3) + 4;
#pragma unroll 4
    for (int j = 0; j < KK; j++) {
        const float* vr = &g_yv[nid[wid][j]*CC];
        acc0 = fmaf(att[wid][j*8 + h0], vr[lane],      acc0);
        acc1 = fmaf(att[wid][j*8 + h1], vr[lane + 32], acc1);
    }
    acc0 -= g_yv[bn*CC + lane];
    acc1 -= g_yv[bn*CC + lane + 32];

    const float* xb = x + b*CC*NN;
    g_s1[bn*CC + lane]      = xb[lane*NN + n]        + acc0;
    g_s1[bn*CC + lane + 32] = xb[(lane + 32)*NN + n] + acc1;
}

// ---------------- 5/8) BN stats (per channel over B*N) ----------------
__global__ void k_stats(int which) {
    const float* s = which ? g_s2 : g_s1;
    int c = blockIdx.x, tid = threadIdx.x;
    float sum = 0.f, sq = 0.f;
    for (int r = tid; r < BN; r += 256) {
        float v = s[r*CC + c];
        sum += v; sq = fmaf(v, v, sq);
    }
    __shared__ float ss[256], sq2[256];
    ss[tid] = sum; sq2[tid] = sq;
    __syncthreads();
    for (int st = 128; st > 0; st >>= 1) {
        if (tid < st) { ss[tid] += ss[tid + st]; sq2[tid] += sq2[tid + st]; }
        __syncthreads();
    }
    if (tid == 0) {
        float m   = ss[0] * (1.f/BN);
        float var = sq2[0] * (1.f/BN) - m*m;
        float r   = rsqrtf(var + 1e-5f);
        if (which) { g_mean2[c] = m; g_rstd2[c] = r; }
        else       { g_mean1[c] = m; g_rstd1[c] = r; }
    }
}

// ---------------- 6) BN1 + h = lrelu(W1 @ x1); store x1, h ----------------
__global__ void k_ffn1(const float* __restrict__ gg1, const float* __restrict__ bb1) {
    __shared__ float x1sh[CC*32];   // [c][p], 8KB
    __shared__ float Wsh[CC*128];   // [cin][cout], 32KB
    int tid = threadIdx.x;
    int bn0 = blockIdx.x * 32;
    for (int i = tid; i < CC*128; i += 256) Wsh[i] = g_W1T[i];
    for (int i = tid; i < CC*32; i += 256) {
        int c = i >> 5, p = i & 31;
        float v = g_s1[(bn0 + p)*CC + c];
        float x1 = gg1[c]*(v - g_mean1[c])*g_rstd1[c] + bb1[c];
        x1sh[c*32 + p] = x1;
        g_x1[(bn0 + p)*CC + c] = x1;
    }
    __syncthreads();
    int p = tid & 31, og = (tid >> 5) * 16;
    float acc[16];
#pragma unroll
    for (int u = 0; u < 16; u++) acc[u] = 0.f;
#pragma unroll 8
    for (int k = 0; k < CC; k++) {
        float xv = x1sh[k*32 + p];
#pragma unroll
        for (int u = 0; u < 16; u++) acc[u] = fmaf(xv, Wsh[k*128 + og + u], acc[u]);
    }
    float* ho = g_h + (bn0 + p)*128 + og;
#pragma unroll
    for (int u4 = 0; u4 < 4; u4++) {
        float4 o;
        o.x = acc[u4*4+0] > 0.f ? acc[u4*4+0] : 0.2f*acc[u4*4+0];
        o.y = acc[u4*4+1] > 0.f ? acc[u4*4+1] : 0.2f*acc[u4*4+1];
        o.z = acc[u4*4+2] > 0.f ? acc[u4*4+2] : 0.2f*acc[u4*4+2];
        o.w = acc[u4*4+3] > 0.f ? acc[u4*4+3] : 0.2f*acc[u4*4+3];
        *(float4*)&ho[u4*4] = o;
    }
}

// ---------------- 7) s2 = x1 + W2 @ h ----------------
__global__ void k_ffn2() {
    __shared__ float hsh[128*16];   // [k][p], 8KB
    __shared__ float Wsh[128*CC];   // [k][cout], 32KB
    int tid = threadIdx.x;
    int bn0 = blockIdx.x * 16;
    for (int i = tid; i < 128*CC; i += 256) Wsh[i] = g_W2T[i];
    for (int i = tid; i < 128*16; i += 256) {
        int k = i >> 4, p = i & 15;
        hsh[k*16 + p] = g_h[(bn0 + p)*128 + k];
    }
    __syncthreads();
    int p = tid & 15, cg = (tid >> 4) * 4;
    float4 acc = make_float4(0.f, 0.f, 0.f, 0.f);
#pragma unroll 8
    for (int k = 0; k < 128; k++) {
        float hv = hsh[k*16 + p];
        float4 wv = *(const float4*)&Wsh[k*CC + cg];
        acc.x = fmaf(hv, wv.x, acc.x);
        acc.y = fmaf(hv, wv.y, acc.y);
        acc.z = fmaf(hv, wv.z, acc.z);
        acc.w = fmaf(hv, wv.w, acc.w);
    }
    int bn = bn0 + p;
    float4 x1v = *(const float4*)&g_x1[bn*CC + cg];
    float4 o;
    o.x = x1v.x + acc.x; o.y = x1v.y + acc.y;
    o.z = x1v.z + acc.z; o.w = x1v.w + acc.w;
    *(float4*)&g_s2[bn*CC + cg] = o;
}

// ---------------- 9) BN2 + transpose to (B, C, N) output ----------------
__global__ void k_final(const float* __restrict__ gg2, const float* __restrict__ bb2,
                        float* __restrict__ out) {
    int i = blockIdx.x * 256 + threadIdx.x;      // 0 .. B*C*N-1
    int n = i & (NN - 1);
    int c = (i >> 11) & 63;
    int b = i >> 17;
    float v = g_s2[(b*NN + n)*CC + c];
    out[i] = gg2[c]*(v - g_mean2[c])*g_rstd2[c] + bb2[c];
}

// ---------------- launcher ----------------
extern "C" void kernel_launch(void* const* d_in, const int* in_sizes, int n_in,
                              void* d_out, int out_size) {
    const float* x  = (const float*)d_in[0];
    const float* Wq = (const float*)d_in[1];
    const float* Wk = (const float*)d_in[2];
    const float* Wv = (const float*)d_in[3];
    const float* W1 = (const float*)d_in[4];
    const float* W2 = (const float*)d_in[5];
    const float* g1 = (const float*)d_in[6];
    const float* b1 = (const float*)d_in[7];
    const float* g2 = (const float*)d_in[8];
    const float* b2 = (const float*)d_in[9];
    float* out = (float*)d_out;

    k_prep <<<32, 256>>>(Wq, Wk, Wv, W1, W2);
    k_xx   <<<dim3(NN/256, BB), 256>>>(x);
    k_knn  <<<dim3(NN/64, BB), 64>>>(x);
    k_proj <<<dim3(NN/64, BB), 256>>>(x);
    k_attn <<<BN/8, 256>>>(x);
    k_stats<<<CC, 256>>>(0);
    k_ffn1 <<<BN/32, 256>>>(g1, b1);
    k_ffn2 <<<BN/16, 256>>>();
    k_stats<<<CC, 256>>>(1);
    k_final<<<(BB*CC*NN)/256, 256>>>(g2, b2, out);
}

// round 6
// speedup vs baseline: 1.1054x; 1.1054x over previous
#include <cuda_runtime.h>
#include <math.h>

#define BB 8
#define CC 64
#define NN 2048
#define KK 32
#define BN (BB*NN)   // 16384 points

// ---------------- device scratch (no allocations allowed) ----------------
__device__ float g_xx[BN];
__device__ int   g_idx[BN*KK];
__device__ float g_WT [3*CC*CC];   // Wq/Wk/Wv transposed: [w][cin][cout]
__device__ float g_W1T[CC*128];    // [cin][cout]
__device__ float g_W2T[128*CC];    // [cin][cout]
__device__ float g_q [BN*CC];      // point-major [bn][c]
__device__ float g_yk[BN*CC];
__device__ float g_yv[BN*CC];
__device__ float g_s1[BN*CC];      // x + attn_out (pre-BN1), point-major
__device__ float g_x1[BN*CC];      // BN1 output, point-major
__device__ float g_h [BN*128];     // lrelu(W1@x1), point-major
__device__ float g_s2[BN*CC];      // x1 + ff (pre-BN2), point-major
__device__ float g_mean1[CC], g_rstd1[CC], g_mean2[CC], g_rstd2[CC];

// packed fp32x2 FMA (Blackwell FFMA2): d = a*b + c on both lanes
#define FMA_F32X2(d, a, b, c) \
    asm("fma.rn.f32x2 %0, %1, %2, %3;" : "=l"(d) : "l"(a), "l"(b), "l"(c))

// order-preserving float -> uint32 key
__device__ __forceinline__ unsigned fkey(float f) {
    unsigned b = __float_as_uint(f);
    return b ^ ((unsigned)((int)b >> 31) | 0x80000000u);
}

// ---------------- 0) transpose weights ----------------
__global__ void k_prep(const float* __restrict__ Wq, const float* __restrict__ Wk,
                       const float* __restrict__ Wv, const float* __restrict__ W1,
                       const float* __restrict__ W2) {
    int i = blockIdx.x * 256 + threadIdx.x;
    if (i < CC*CC) {
        int o = i >> 6, ci = i & 63;
        g_WT[0*CC*CC + ci*CC + o] = Wq[i];
        g_WT[1*CC*CC + ci*CC + o] = Wk[i];
        g_WT[2*CC*CC + ci*CC + o] = Wv[i];
    }
    if (i < 128*CC) {
        int o = i >> 6, ci = i & 63;      // W1[o][ci], o<128
        g_W1T[ci*128 + o] = W1[i];
        int co = i >> 7, k2 = i & 127;    // W2[co][k2], co<64
        g_W2T[k2*CC + co] = W2[i];
    }
}

// ---------------- 1) per-point squared norms ----------------
__global__ void k_xx(const float* __restrict__ x) {
    int b = blockIdx.y;
    int n = blockIdx.x * 256 + threadIdx.x;
    const float* xb = x + b*CC*NN;
    float s = 0.f;
#pragma unroll
    for (int c = 0; c < CC; c++) { float v = xb[c*NN + n]; s = fmaf(v, v, s); }
    g_xx[b*NN + n] = s;
}

// ---------------- 2) KNN v2: FFMA2 distances + smem min-heap top-32 ----------------
// 128 threads/block (thread = query), grid (NN/128, BB) = (16, 8).
// Candidate tile 32 wide; per-thread 33-slot min-heap (slot 32 = +inf sentinel)
// in smem, layout [pos][tid] -> conflict-free.
#define HP(p) sh_heap[(p)*128 + tid]

__global__ __launch_bounds__(128, 1) void k_knn(const float* __restrict__ x) {
    __shared__ __align__(16) float sh_c[CC*32];           // [c][m] candidate tile (8KB)
    __shared__ float sh_xx[32];
    __shared__ unsigned long long sh_heap[33*128];        // 33KB

    int tid = threadIdx.x;
    int b   = blockIdx.y;
    int n   = blockIdx.x * 128 + tid;
    const float* xb = x + b*CC*NN;

    // query, duplicated into packed (q,q) pairs
    unsigned long long qq[CC];
#pragma unroll
    for (int c = 0; c < CC; c++) {
        float qc = xb[c*NN + n];
        asm("mov.b64 %0, {%1, %1};" : "=l"(qq[c]) : "f"(qc));
    }
    float xxn = g_xx[b*NN + n];

    // heap init: keys 0 (below any real key); sentinel at slot 32
#pragma unroll
    for (int p = 0; p < 32; p++) HP(p) = 0ull;
    HP(32) = ~0ull;
    unsigned rootk = 0u;

    for (int t = 0; t < NN/32; t++) {
        int m0 = t * 32;
        __syncthreads();
        for (int i = tid; i < CC*32; i += 128) {
            int c = i >> 5, m = i & 31;
            sh_c[c*32 + m] = xb[c*NN + m0 + m];
        }
        if (tid < 32) sh_xx[tid] = g_xx[b*NN + m0 + tid];
        __syncthreads();

#pragma unroll 1
        for (int m4 = 0; m4 < 8; m4++) {
            unsigned long long acc01 = 0ull, acc23 = 0ull;  // packed (0,0)
#pragma unroll
            for (int c = 0; c < CC; c++) {
                ulonglong2 s = *(const ulonglong2*)&sh_c[c*32 + m4*4];
                FMA_F32X2(acc01, qq[c], s.x, acc01);
                FMA_F32X2(acc23, qq[c], s.y, acc23);
            }
            float a0, a1, a2, a3;
            asm("mov.b64 {%0, %1}, %2;" : "=f"(a0), "=f"(a1) : "l"(acc01));
            asm("mov.b64 {%0, %1}, %2;" : "=f"(a2), "=f"(a3) : "l"(acc23));
            float vals[4];
            vals[0] = fmaf(2.f, a0, -xxn) - sh_xx[m4*4 + 0];
            vals[1] = fmaf(2.f, a1, -xxn) - sh_xx[m4*4 + 1];
            vals[2] = fmaf(2.f, a2, -xxn) - sh_xx[m4*4 + 2];
            vals[3] = fmaf(2.f, a3, -xxn) - sh_xx[m4*4 + 3];
#pragma unroll
            for (int u = 0; u < 4; u++) {
                unsigned key = fkey(vals[u]);
                if (key > rootk) {
                    unsigned long long cur =
                        ((unsigned long long)key << 32) | (unsigned)(m0 + m4*4 + u);
                    int p = 0;
                    bool act = true;
                    unsigned long long nroot = cur;
#pragma unroll
                    for (int l = 0; l < 5; l++) {
                        int c1 = 2*p + 1;
                        bool valid = act && (c1 < 32);
                        unsigned long long k1 = valid ? HP(c1)   : ~0ull;
                        unsigned long long k2 = valid ? HP(c1+1) : ~0ull;
                        bool lt = k1 < k2;
                        unsigned long long ks = lt ? k1 : k2;
                        int cs = lt ? c1 : c1 + 1;
                        bool sw = valid && (cur > ks);
                        if (sw) HP(p) = ks;
                        if (l == 0) nroot = sw ? ks : cur;
                        p = sw ? cs : p;
                        act = sw;
                    }
                    HP(p) = cur;
                    rootk = (unsigned)(nroot >> 32);
                }
            }
        }
    }

    int* op = g_idx + (b*NN + n)*KK;
#pragma unroll
    for (int i = 0; i < KK; i++) op[i] = (int)(unsigned)HP(i);
}

// ---------------- 3) projections q/yk/yv = W @ x (point-major out) ----------------
__global__ void k_proj(const float* __restrict__ x) {
    __shared__ float shx[CC*64];   // [c][p]
    __shared__ float shW[CC*CC];   // [cin][cout]
    int b  = blockIdx.y;
    int n0 = blockIdx.x * 64;
    int tid = threadIdx.x;
    const float* xb = x + b*CC*NN;
    for (int i = tid; i < CC*64; i += 256) {
        int c = i >> 6, p = i & 63;
        shx[c*64 + p] = xb[c*NN + n0 + p];
    }
    int p  = tid & 63;
    int cg = (tid >> 6) << 4;           // 16 output channels per thread
    int bn = b*NN + n0 + p;
    for (int w = 0; w < 3; w++) {
        __syncthreads();
        for (int i = tid; i < CC*CC; i += 256) shW[i] = g_WT[w*CC*CC + i];
        __syncthreads();
        float4 acc[4];
#pragma unroll
        for (int g = 0; g < 4; g++) acc[g] = make_float4(0.f, 0.f, 0.f, 0.f);
#pragma unroll
        for (int k = 0; k < CC; k++) {
            float xv = shx[k*64 + p];
#pragma unroll
            for (int g = 0; g < 4; g++) {
                float4 wv = *(const float4*)&shW[k*CC + cg + g*4];
                acc[g].x = fmaf(xv, wv.x, acc[g].x);
                acc[g].y = fmaf(xv, wv.y, acc[g].y);
                acc[g].z = fmaf(xv, wv.z, acc[g].z);
                acc[g].w = fmaf(xv, wv.w, acc[g].w);
            }
        }
        float* dst = (w == 0 ? g_q : (w == 1 ? g_yk : g_yv)) + bn*CC + cg;
#pragma unroll
        for (int g = 0; g < 4; g++) *(float4*)&dst[g*4] = acc[g];
    }
}

// ---------------- 4) attention (warp per point) + residual -> s1 ----------------
__global__ void k_attn(const float* __restrict__ x) {
    __shared__ float qsh[8][64];
    __shared__ float ykn[8][64];
    __shared__ float att[8][KK*8];
    __shared__ int   nid[8][KK];
    int tid  = threadIdx.x;
    int wid  = tid >> 5, lane = tid & 31;
    int bn   = blockIdx.x * 8 + wid;
    int b    = bn >> 11;
    int n    = bn & (NN - 1);

    qsh[wid][lane]      = g_q [bn*CC + lane];
    qsh[wid][lane + 32] = g_q [bn*CC + lane + 32];
    ykn[wid][lane]      = g_yk[bn*CC + lane];
    ykn[wid][lane + 32] = g_yk[bn*CC + lane + 32];
    int gn = b*NN + g_idx[bn*KK + lane];   // global row of this lane's neighbor
    nid[wid][lane] = gn;
    __syncwarp();

    const float4* kr = (const float4*)&g_yk[gn*CC];
    float e[8];
#pragma unroll
    for (int h = 0; h < 8; h++) e[h] = 0.f;
#pragma unroll
    for (int c4 = 0; c4 < 16; c4++) {
        float4 kv = kr[c4];
        int c = c4*4, h = c4 >> 1;
        float t = (kv.x - ykn[wid][c+0]) * qsh[wid][c+0];
        t = fmaf(kv.y - ykn[wid][c+1], qsh[wid][c+1], t);
        t = fmaf(kv.z - ykn[wid][c+2], qsh[wid][c+2], t);
        t = fmaf(kv.w - ykn[wid][c+3], qsh[wid][c+3], t);
        e[h] += t;
    }
    const float sc = 0.3535533905932738f;  // 1/sqrt(8)
#pragma unroll
    for (int h = 0; h < 8; h++) {
        float eh = e[h] * sc;
        float mx = eh;
#pragma unroll
        for (int o = 16; o > 0; o >>= 1) mx = fmaxf(mx, __shfl_xor_sync(0xffffffffu, mx, o));
        float ex = __expf(eh - mx);
        float sm = ex;
#pragma unroll
        for (int o = 16; o > 0; o >>= 1) sm += __shfl_xor_sync(0xffffffffu, sm, o);
        att[wid][lane*8 + h] = ex / sm;
    }
    __syncwarp();

    // out[c] = sum_j a[j][c>>3]*yv_j[c] - yv_center[c]  (softmax sums to 1)
    float acc0 = 0.f, acc1 = 0.f;
    int h0 = lane >> 3, h1 = (lane >> 3) + 4;
#pragma unroll 4
    for (int j = 0; j < KK; j++) {
        const float* vr = &g_yv[nid[wid][j]*CC];
        acc0 = fmaf(att[wid][j*8 + h0], vr[lane],      acc0);
        acc1 = fmaf(att[wid][j*8 + h1], vr[lane + 32], acc1);
    }
    acc0 -= g_yv[bn*CC + lane];
    acc1 -= g_yv[bn*CC + lane + 32];

    const float* xb = x + b*CC*NN;
    g_s1[bn*CC + lane]      = xb[lane*NN + n]        + acc0;
    g_s1[bn*CC + lane + 32] = xb[(lane + 32)*NN + n] + acc1;
}

// ---------------- 5/8) BN stats (per channel over B*N) ----------------
__global__ void k_stats(int which) {
    const float* s = which ? g_s2 : g_s1;
    int c = blockIdx.x, tid = threadIdx.x;
    float sum = 0.f, sq = 0.f;
    for (int r = tid; r < BN; r += 256) {
        float v = s[r*CC + c];
        sum += v; sq = fmaf(v, v, sq);
    }
    __shared__ float ss[256], sq2[256];
    ss[tid] = sum; sq2[tid] = sq;
    __syncthreads();
    for (int st = 128; st > 0; st >>= 1) {
        if (tid < st) { ss[tid] += ss[tid + st]; sq2[tid] += sq2[tid + st]; }
        __syncthreads();
    }
    if (tid == 0) {
        float m   = ss[0] * (1.f/BN);
        float var = sq2[0] * (1.f/BN) - m*m;
        float r   = rsqrtf(var + 1e-5f);
        if (which) { g_mean2[c] = m; g_rstd2[c] = r; }
        else       { g_mean1[c] = m; g_rstd1[c] = r; }
    }
}

// ---------------- 6) BN1 + h = lrelu(W1 @ x1); store x1, h ----------------
__global__ void k_ffn1(const float* __restrict__ gg1, const float* __restrict__ bb1) {
    __shared__ float x1sh[CC*32];   // [c][p], 8KB
    __shared__ float Wsh[CC*128];   // [cin][cout], 32KB
    int tid = threadIdx.x;
    int bn0 = blockIdx.x * 32;
    for (int i = tid; i < CC*128; i += 256) Wsh[i] = g_W1T[i];
    for (int i = tid; i < CC*32; i += 256) {
        int c = i >> 5, p = i & 31;
        float v = g_s1[(bn0 + p)*CC + c];
        float x1 = gg1[c]*(v - g_mean1[c])*g_rstd1[c] + bb1[c];
        x1sh[c*32 + p] = x1;
        g_x1[(bn0 + p)*CC + c] = x1;
    }
    __syncthreads();
    int p = tid & 31, og = (tid >> 5) * 16;
    float acc[16];
#pragma unroll
    for (int u = 0; u < 16; u++) acc[u] = 0.f;
#pragma unroll 8
    for (int k = 0; k < CC; k++) {
        float xv = x1sh[k*32 + p];
#pragma unroll
        for (int u = 0; u < 16; u++) acc[u] = fmaf(xv, Wsh[k*128 + og + u], acc[u]);
    }
    float* ho = g_h + (bn0 + p)*128 + og;
#pragma unroll
    for (int u4 = 0; u4 < 4; u4++) {
        float4 o;
        o.x = acc[u4*4+0] > 0.f ? acc[u4*4+0] : 0.2f*acc[u4*4+0];
        o.y = acc[u4*4+1] > 0.f ? acc[u4*4+1] : 0.2f*acc[u4*4+1];
        o.z = acc[u4*4+2] > 0.f ? acc[u4*4+2] : 0.2f*acc[u4*4+2];
        o.w = acc[u4*4+3] > 0.f ? acc[u4*4+3] : 0.2f*acc[u4*4+3];
        *(float4*)&ho[u4*4] = o;
    }
}

// ---------------- 7) s2 = x1 + W2 @ h ----------------
__global__ void k_ffn2() {
    __shared__ float hsh[128*16];   // [k][p], 8KB
    __shared__ float Wsh[128*CC];   // [k][cout], 32KB
    int tid = threadIdx.x;
    int bn0 = blockIdx.x * 16;
    for (int i = tid; i < 128*CC; i += 256) Wsh[i] = g_W2T[i];
    for (int i = tid; i < 128*16; i += 256) {
        int k = i >> 4, p = i & 15;
        hsh[k*16 + p] = g_h[(bn0 + p)*128 + k];
    }
    __syncthreads();
    int p = tid & 15, cg = (tid >> 4) * 4;
    float4 acc = make_float4(0.f, 0.f, 0.f, 0.f);
#pragma unroll 8
    for (int k = 0; k < 128; k++) {
        float hv = hsh[k*16 + p];
        float4 wv = *(const float4*)&Wsh[k*CC + cg];
        acc.x = fmaf(hv, wv.x, acc.x);
        acc.y = fmaf(hv, wv.y, acc.y);
        acc.z = fmaf(hv, wv.z, acc.z);
        acc.w = fmaf(hv, wv.w, acc.w);
    }
    int bn = bn0 + p;
    float4 x1v = *(const float4*)&g_x1[bn*CC + cg];
    float4 o;
    o.x = x1v.x + acc.x; o.y = x1v.y + acc.y;
    o.z = x1v.z + acc.z; o.w = x1v.w + acc.w;
    *(float4*)&g_s2[bn*CC + cg] = o;
}

// ---------------- 9) BN2 + transpose to (B, C, N) output ----------------
__global__ void k_final(const float* __restrict__ gg2, const float* __restrict__ bb2,
                        float* __restrict__ out) {
    int i = blockIdx.x * 256 + threadIdx.x;      // 0 .. B*C*N-1
    int n = i & (NN - 1);
    int c = (i >> 11) & 63;
    int b = i >> 17;
    float v = g_s2[(b*NN + n)*CC + c];
    out[i] = gg2[c]*(v - g_mean2[c])*g_rstd2[c] + bb2[c];
}

// ---------------- launcher ----------------
extern "C" void kernel_launch(void* const* d_in, const int* in_sizes, int n_in,
                              void* d_out, int out_size) {
    const float* x  = (const float*)d_in[0];
    const float* Wq = (const float*)d_in[1];
    const float* Wk = (const float*)d_in[2];
    const float* Wv = (const float*)d_in[3];
    const float* W1 = (const float*)d_in[4];
    const float* W2 = (const float*)d_in[5];
    const float* g1 = (const float*)d_in[6];
    const float* b1 = (const float*)d_in[7];
    const float* g2 = (const float*)d_in[8];
    const float* b2 = (const float*)d_in[9];
    float* out = (float*)d_out;

    k_prep <<<32, 256>>>(Wq, Wk, Wv, W1, W2);
    k_xx   <<<dim3(NN/256, BB), 256>>>(x);
    k_knn  <<<dim3(NN/128, BB), 128>>>(x);
    k_proj <<<dim3(NN/64, BB), 256>>>(x);
    k_attn <<<BN/8, 256>>>(x);
    k_stats<<<CC, 256>>>(0);
    k_ffn1 <<<BN/32, 256>>>(g1, b1);
    k_ffn2 <<<BN/16, 256>>>();
    k_stats<<<CC, 256>>>(1);
    k_final<<<(BB*CC*NN)/256, 256>>>(g2, b2, out);
}

// round 7
// speedup vs baseline: 1.4006x; 1.2671x over previous
#include <cuda_runtime.h>
#include <math.h>

#define BB 8
#define CC 64
#define NN 2048
#define KK 32
#define BN (BB*NN)   // 16384 points
#define NSPLIT 4
#define CPS (NN/NSPLIT)   // 512 candidates per split

// ---------------- device scratch (no allocations allowed) ----------------
__device__ float g_xx[BN];
__device__ int   g_idx[BN*KK];
__device__ unsigned long long g_part[BN*NSPLIT*KK];   // per-split top-32 (key|idx)
__device__ float g_WT [3*CC*CC];   // Wq/Wk/Wv transposed: [w][cin][cout]
__device__ float g_W1T[CC*128];    // [cin][cout]
__device__ float g_W2T[128*CC];    // [cin][cout]
__device__ float g_q [BN*CC];      // point-major [bn][c]
__device__ float g_yk[BN*CC];
__device__ float g_yv[BN*CC];
__device__ float g_s1[BN*CC];      // x + attn_out (pre-BN1), point-major
__device__ float g_x1[BN*CC];      // BN1 output, point-major
__device__ float g_h [BN*128];     // lrelu(W1@x1), point-major
__device__ float g_s2[BN*CC];      // x1 + ff (pre-BN2), point-major
__device__ float g_mean1[CC], g_rstd1[CC], g_mean2[CC], g_rstd2[CC];

// packed fp32x2 FMA (Blackwell FFMA2): d = a*b + c on both lanes
#define FMA_F32X2(d, a, b, c) \
    asm("fma.rn.f32x2 %0, %1, %2, %3;" : "=l"(d) : "l"(a), "l"(b), "l"(c))

// order-preserving float -> uint32 key
__device__ __forceinline__ unsigned fkey(float f) {
    unsigned b = __float_as_uint(f);
    return b ^ ((unsigned)((int)b >> 31) | 0x80000000u);
}

// ---------------- 0) transpose weights ----------------
__global__ void k_prep(const float* __restrict__ Wq, const float* __restrict__ Wk,
                       const float* __restrict__ Wv, const float* __restrict__ W1,
                       const float* __restrict__ W2) {
    int i = blockIdx.x * 256 + threadIdx.x;
    if (i < CC*CC) {
        int o = i >> 6, ci = i & 63;
        g_WT[0*CC*CC + ci*CC + o] = Wq[i];
        g_WT[1*CC*CC + ci*CC + o] = Wk[i];
        g_WT[2*CC*CC + ci*CC + o] = Wv[i];
    }
    if (i < 128*CC) {
        int o = i >> 6, ci = i & 63;      // W1[o][ci], o<128
        g_W1T[ci*128 + o] = W1[i];
        int co = i >> 7, k2 = i & 127;    // W2[co][k2], co<64
        g_W2T[k2*CC + co] = W2[i];
    }
}

// ---------------- 1) per-point squared norms ----------------
__global__ void k_xx(const float* __restrict__ x) {
    int b = blockIdx.y;
    int n = blockIdx.x * 256 + threadIdx.x;
    const float* xb = x + b*CC*NN;
    float s = 0.f;
#pragma unroll
    for (int c = 0; c < CC; c++) { float v = xb[c*NN + n]; s = fmaf(v, v, s); }
    g_xx[b*NN + n] = s;
}

// ---------------- 2) KNN pass 1: per-split top-32 ----------------
// 128 threads/block (thread = query), grid (NN/128, BB, NSPLIT).
// Candidate tile [m][c] (pad 68); FFMA2 over channel pairs; per-thread
// 33-slot smem min-heap (slot 32 = +inf sentinel), layout [pos][tid].
#define HP(p) sh_heap[(p)*128 + tid]
#define CPAD 68

__global__ __launch_bounds__(128, 4) void k_knn(const float* __restrict__ x) {
    __shared__ __align__(16) float sh_c[32*CPAD];         // [m][c] candidate tile
    __shared__ float sh_xx[32];
    __shared__ unsigned long long sh_heap[33*128];        // 33.8KB

    int tid = threadIdx.x;
    int b   = blockIdx.y;
    int n   = blockIdx.x * 128 + tid;
    int cand0 = blockIdx.z * CPS;
    const float* xb = x + b*CC*NN;

    // query as packed channel pairs (q[2k], q[2k+1])
    unsigned long long qp[32];
#pragma unroll
    for (int k = 0; k < 32; k++) {
        float f0 = xb[(2*k  )*NN + n];
        float f1 = xb[(2*k+1)*NN + n];
        asm("mov.b64 %0, {%1, %2};" : "=l"(qp[k]) : "f"(f0), "f"(f1));
    }
    float xxn = g_xx[b*NN + n];

#pragma unroll
    for (int p = 0; p < 32; p++) HP(p) = 0ull;
    HP(32) = ~0ull;
    unsigned rootk = 0u;

    for (int t = 0; t < CPS/32; t++) {
        int m0 = cand0 + t * 32;
        __syncthreads();
        for (int i = tid; i < 32*CC; i += 128) {
            int m = i & 31, c = i >> 5;
            sh_c[m*CPAD + c] = xb[c*NN + m0 + m];
        }
        if (tid < 32) sh_xx[tid] = g_xx[b*NN + m0 + tid];
        __syncthreads();

#pragma unroll 1
        for (int m4 = 0; m4 < 8; m4++) {
            unsigned long long acc[4] = {0ull, 0ull, 0ull, 0ull};
#pragma unroll
            for (int c4 = 0; c4 < 16; c4++) {
#pragma unroll
                for (int j = 0; j < 4; j++) {
                    ulonglong2 s = *(const ulonglong2*)&sh_c[(m4*4+j)*CPAD + c4*4];
                    FMA_F32X2(acc[j], qp[2*c4],   s.x, acc[j]);
                    FMA_F32X2(acc[j], qp[2*c4+1], s.y, acc[j]);
                }
            }
#pragma unroll
            for (int j = 0; j < 4; j++) {
                float lo, hi;
                asm("mov.b64 {%0, %1}, %2;" : "=f"(lo), "=f"(hi) : "l"(acc[j]));
                float a   = lo + hi;
                float val = fmaf(2.f, a, -xxn) - sh_xx[m4*4 + j];
                unsigned key = fkey(val);
                if (key > rootk) {
                    unsigned long long cur =
                        ((unsigned long long)key << 32) | (unsigned)(m0 + m4*4 + j);
                    int p = 0;
                    bool act = true;
                    unsigned long long nroot = cur;
#pragma unroll
                    for (int l = 0; l < 5; l++) {
                        int c1 = 2*p + 1;
                        bool valid = act && (c1 < 32);
                        unsigned long long k1 = valid ? HP(c1)   : ~0ull;
                        unsigned long long k2 = valid ? HP(c1+1) : ~0ull;
                        bool lt = k1 < k2;
                        unsigned long long ks = lt ? k1 : k2;
                        int cs = lt ? c1 : c1 + 1;
                        bool sw = valid && (cur > ks);
                        if (sw) HP(p) = ks;
                        if (l == 0) nroot = sw ? ks : cur;
                        p = sw ? cs : p;
                        act = sw;
                    }
                    HP(p) = cur;
                    rootk = (unsigned)(nroot >> 32);
                }
            }
        }
    }

    unsigned long long* op = g_part + (b*NN + n)*(NSPLIT*KK) + blockIdx.z*KK;
#pragma unroll
    for (int p = 0; p < KK; p++) op[p] = HP(p);
}

// ---------------- 2b) KNN pass 2: merge 4x32 -> top-32 ----------------
// warp per query; 32 iterations of 64-bit warp max-extract (keys unique).
__global__ void k_mrg() {
    int tid  = threadIdx.x;
    int wid  = tid >> 5, lane = tid & 31;
    int bn   = blockIdx.x * 8 + wid;
    const unsigned long long* src = g_part + bn*(NSPLIT*KK);

    unsigned long long v[NSPLIT];
#pragma unroll
    for (int j = 0; j < NSPLIT; j++) v[j] = src[j*32 + lane];

    int* op = g_idx + bn*KK;
#pragma unroll 1
    for (int i = 0; i < KK; i++) {
        unsigned long long m01 = v[0] > v[1] ? v[0] : v[1];
        unsigned long long m23 = v[2] > v[3] ? v[2] : v[3];
        unsigned long long lm  = m01 > m23 ? m01 : m23;
        unsigned long long wm  = lm;
#pragma unroll
        for (int o = 16; o > 0; o >>= 1) {
            unsigned long long t = __shfl_xor_sync(0xffffffffu, wm, o);
            wm = t > wm ? t : wm;
        }
        if (lm == wm) {     // unique owner (keys embed distinct idx)
            if      (v[0] == wm) v[0] = 0ull;
            else if (v[1] == wm) v[1] = 0ull;
            else if (v[2] == wm) v[2] = 0ull;
            else if (v[3] == wm) v[3] = 0ull;
        }
        if (lane == i) op[i] = (int)(unsigned)wm;
    }
}

// ---------------- 3) projections q/yk/yv = W @ x (point-major out) ----------------
__global__ void k_proj(const float* __restrict__ x) {
    __shared__ float shx[CC*64];   // [c][p]
    __shared__ float shW[CC*CC];   // [cin][cout]
    int b  = blockIdx.y;
    int n0 = blockIdx.x * 64;
    int tid = threadIdx.x;
    const float* xb = x + b*CC*NN;
    for (int i = tid; i < CC*64; i += 256) {
        int c = i >> 6, p = i & 63;
        shx[c*64 + p] = xb[c*NN + n0 + p];
    }
    int p  = tid & 63;
    int cg = (tid >> 6) << 4;           // 16 output channels per thread
    int bn = b*NN + n0 + p;
    for (int w = 0; w < 3; w++) {
        __syncthreads();
        for (int i = tid; i < CC*CC; i += 256) shW[i] = g_WT[w*CC*CC + i];
        __syncthreads();
        float4 acc[4];
#pragma unroll
        for (int g = 0; g < 4; g++) acc[g] = make_float4(0.f, 0.f, 0.f, 0.f);
#pragma unroll
        for (int k = 0; k < CC; k++) {
            float xv = shx[k*64 + p];
#pragma unroll
            for (int g = 0; g < 4; g++) {
                float4 wv = *(const float4*)&shW[k*CC + cg + g*4];
                acc[g].x = fmaf(xv, wv.x, acc[g].x);
                acc[g].y = fmaf(xv, wv.y, acc[g].y);
                acc[g].z = fmaf(xv, wv.z, acc[g].z);
                acc[g].w = fmaf(xv, wv.w, acc[g].w);
            }
        }
        float* dst = (w == 0 ? g_q : (w == 1 ? g_yk : g_yv)) + bn*CC + cg;
#pragma unroll
        for (int g = 0; g < 4; g++) *(float4*)&dst[g*4] = acc[g];
    }
}

// ---------------- 4) attention (warp per point) + residual -> s1 ----------------
__global__ void k_attn(const float* __restrict__ x) {
    __shared__ float qsh[8][64];
    __shared__ float ykn[8][64];
    __shared__ float att[8][KK*8];
    __shared__ int   nid[8][KK];
    int tid  = threadIdx.x;
    int wid  = tid >> 5, lane = tid & 31;
    int bn   = blockIdx.x * 8 + wid;
    int b    = bn >> 11;
    int n    = bn & (NN - 1);

    qsh[wid][lane]      = g_q [bn*CC + lane];
    qsh[wid][lane + 32] = g_q [bn*CC + lane + 32];
    ykn[wid][lane]      = g_yk[bn*CC + lane];
    ykn[wid][lane + 32] = g_yk[bn*CC + lane + 32];
    int gn = b*NN + g_idx[bn*KK + lane];   // global row of this lane's neighbor
    nid[wid][lane] = gn;
    __syncwarp();

    const float4* kr = (const float4*)&g_yk[gn*CC];
    float e[8];
#pragma unroll
    for (int h = 0; h < 8; h++) e[h] = 0.f;
#pragma unroll
    for (int c4 = 0; c4 < 16; c4++) {
        float4 kv = kr[c4];
        int c = c4*4, h = c4 >> 1;
        float t = (kv.x - ykn[wid][c+0]) * qsh[wid][c+0];
        t = fmaf(kv.y - ykn[wid][c+1], qsh[wid][c+1], t);
        t = fmaf(kv.z - ykn[wid][c+2], qsh[wid][c+2], t);
        t = fmaf(kv.w - ykn[wid][c+3], qsh[wid][c+3], t);
        e[h] += t;
    }
    const float sc = 0.3535533905932738f;  // 1/sqrt(8)
#pragma unroll
    for (int h = 0; h < 8; h++) {
        float eh = e[h] * sc;
        float mx = eh;
#pragma unroll
        for (int o = 16; o > 0; o >>= 1) mx = fmaxf(mx, __shfl_xor_sync(0xffffffffu, mx, o));
        float ex = __expf(eh - mx);
        float sm = ex;
#pragma unroll
        for (int o = 16; o > 0; o >>= 1) sm += __shfl_xor_sync(0xffffffffu, sm, o);
        att[wid][lane*8 + h] = ex / sm;
    }
    __syncwarp();

    // out[c] = sum_j a[j][c>>3]*yv_j[c] - yv_center[c]  (softmax sums to 1)
    float acc0 = 0.f, acc1 = 0.f;
    int h0 = lane >> 3, h1 = (lane >> 3) + 4;
#pragma unroll 4
    for (int j = 0; j < KK; j++) {
        const float* vr = &g_yv[nid[wid][j]*CC];
        acc0 = fmaf(att[wid][j*8 + h0], vr[lane],      acc0);
        acc1 = fmaf(att[wid][j*8 + h1], vr[lane + 32], acc1);
    }
    acc0 -= g_yv[bn*CC + lane];
    acc1 -= g_yv[bn*CC + lane + 32];

    const float* xb = x + b*CC*NN;
    g_s1[bn*CC + lane]      = xb[lane*NN + n]        + acc0;
    g_s1[bn*CC + lane + 32] = xb[(lane + 32)*NN + n] + acc1;
}

// ---------------- 5/8) BN stats (per channel over B*N) ----------------
__global__ void k_stats(int which) {
    const float* s = which ? g_s2 : g_s1;
    int c = blockIdx.x, tid = threadIdx.x;
    float sum = 0.f, sq = 0.f;
    for (int r = tid; r < BN; r += 256) {
        float v = s[r*CC + c];
        sum += v; sq = fmaf(v, v, sq);
    }
    __shared__ float ss[256], sq2[256];
    ss[tid] = sum; sq2[tid] = sq;
    __syncthreads();
    for (int st = 128; st > 0; st >>= 1) {
        if (tid < st) { ss[tid] += ss[tid + st]; sq2[tid] += sq2[tid + st]; }
        __syncthreads();
    }
    if (tid == 0) {
        float m   = ss[0] * (1.f/BN);
        float var = sq2[0] * (1.f/BN) - m*m;
        float r   = rsqrtf(var + 1e-5f);
        if (which) { g_mean2[c] = m; g_rstd2[c] = r; }
        else       { g_mean1[c] = m; g_rstd1[c] = r; }
    }
}

// ---------------- 6) BN1 + h = lrelu(W1 @ x1); store x1, h ----------------
__global__ void k_ffn1(const float* __restrict__ gg1, const float* __restrict__ bb1) {
    __shared__ float x1sh[CC*32];   // [c][p], 8KB
    __shared__ float Wsh[CC*128];   // [cin][cout], 32KB
    int tid = threadIdx.x;
    int bn0 = blockIdx.x * 32;
    for (int i = tid; i < CC*128; i += 256) Wsh[i] = g_W1T[i];
    for (int i = tid; i < CC*32; i += 256) {
        int c = i >> 5, p = i & 31;
        float v = g_s1[(bn0 + p)*CC + c];
        float x1 = gg1[c]*(v - g_mean1[c])*g_rstd1[c] + bb1[c];
        x1sh[c*32 + p] = x1;
        g_x1[(bn0 + p)*CC + c] = x1;
    }
    __syncthreads();
    int p = tid & 31, og = (tid >> 5) * 16;
    float acc[16];
#pragma unroll
    for (int u = 0; u < 16; u++) acc[u] = 0.f;
#pragma unroll 8
    for (int k = 0; k < CC; k++) {
        float xv = x1sh[k*32 + p];
#pragma unroll
        for (int u = 0; u < 16; u++) acc[u] = fmaf(xv, Wsh[k*128 + og + u], acc[u]);
    }
    float* ho = g_h + (bn0 + p)*128 + og;
#pragma unroll
    for (int u4 = 0; u4 < 4; u4++) {
        float4 o;
        o.x = acc[u4*4+0] > 0.f ? acc[u4*4+0] : 0.2f*acc[u4*4+0];
        o.y = acc[u4*4+1] > 0.f ? acc[u4*4+1] : 0.2f*acc[u4*4+1];
        o.z = acc[u4*4+2] > 0.f ? acc[u4*4+2] : 0.2f*acc[u4*4+2];
        o.w = acc[u4*4+3] > 0.f ? acc[u4*4+3] : 0.2f*acc[u4*4+3];
        *(float4*)&ho[u4*4] = o;
    }
}

// ---------------- 7) s2 = x1 + W2 @ h ----------------
__global__ void k_ffn2() {
    __shared__ float hsh[128*16];   // [k][p], 8KB
    __shared__ float Wsh[128*CC];   // [k][cout], 32KB
    int tid = threadIdx.x;
    int bn0 = blockIdx.x * 16;
    for (int i = tid; i < 128*CC; i += 256) Wsh[i] = g_W2T[i];
    for (int i = tid; i < 128*16; i += 256) {
        int k = i >> 4, p = i & 15;
        hsh[k*16 + p] = g_h[(bn0 + p)*128 + k];
    }
    __syncthreads();
    int p = tid & 15, cg = (tid >> 4) * 4;
    float4 acc = make_float4(0.f, 0.f, 0.f, 0.f);
#pragma unroll 8
    for (int k = 0; k < 128; k++) {
        float hv = hsh[k*16 + p];
        float4 wv = *(const float4*)&Wsh[k*CC + cg];
        acc.x = fmaf(hv, wv.x, acc.x);
        acc.y = fmaf(hv, wv.y, acc.y);
        acc.z = fmaf(hv, wv.z, acc.z);
        acc.w = fmaf(hv, wv.w, acc.w);
    }
    int bn = bn0 + p;
    float4 x1v = *(const float4*)&g_x1[bn*CC + cg];
    float4 o;
    o.x = x1v.x + acc.x; o.y = x1v.y + acc.y;
    o.z = x1v.z + acc.z; o.w = x1v.w + acc.w;
    *(float4*)&g_s2[bn*CC + cg] = o;
}

// ---------------- 9) BN2 + transpose to (B, C, N) output ----------------
__global__ void k_final(const float* __restrict__ gg2, const float* __restrict__ bb2,
                        float* __restrict__ out) {
    int i = blockIdx.x * 256 + threadIdx.x;      // 0 .. B*C*N-1
    int n = i & (NN - 1);
    int c = (i >> 11) & 63;
    int b = i >> 17;
    float v = g_s2[(b*NN + n)*CC + c];
    out[i] = gg2[c]*(v - g_mean2[c])*g_rstd2[c] + bb2[c];
}

// ---------------- launcher ----------------
extern "C" void kernel_launch(void* const* d_in, const int* in_sizes, int n_in,
                              void* d_out, int out_size) {
    const float* x  = (const float*)d_in[0];
    const float* Wq = (const float*)d_in[1];
    const float* Wk = (const float*)d_in[2];
    const float* Wv = (const float*)d_in[3];
    const float* W1 = (const float*)d_in[4];
    const float* W2 = (const float*)d_in[5];
    const float* g1 = (const float*)d_in[6];
    const float* b1 = (const float*)d_in[7];
    const float* g2 = (const float*)d_in[8];
    const float* b2 = (const float*)d_in[9];
    float* out = (float*)d_out;

    k_prep <<<32, 256>>>(Wq, Wk, Wv, W1, W2);
    k_xx   <<<dim3(NN/256, BB), 256>>>(x);
    k_knn  <<<dim3(NN/128, BB, NSPLIT), 128>>>(x);
    k_mrg  <<<BN/8, 256>>>();
    k_proj <<<dim3(NN/64, BB), 256>>>(x);
    k_attn <<<BN/8, 256>>>(x);
    k_stats<<<CC, 256>>>(0);
    k_ffn1 <<<BN/32, 256>>>(g1, b1);
    k_ffn2 <<<BN/16, 256>>>();
    k_stats<<<CC, 256>>>(1);
    k_final<<<(BB*CC*NN)/256, 256>>>(g2, b2, out);
}

// round 8
// speedup vs baseline: 1.4057x; 1.0037x over previous
#include <cuda_runtime.h>
#include <math.h>

#define BB 8
#define CC 64
#define NN 2048
#define KK 32
#define BN (BB*NN)        // 16384 points
#define NSPLIT 8
#define CPS (NN/NSPLIT)   // 256 candidates per split

// ---------------- device scratch (no allocations allowed) ----------------
__device__ float g_xx[BN];
__device__ int   g_idx[BN*KK];
__device__ unsigned long long g_part[NSPLIT*KK*BN];   // [entry][bn] (transposed)
__device__ float g_WT [3*CC*CC];   // Wq/Wk/Wv transposed: [w][cin][cout]
__device__ float g_W1T[CC*128];    // [cin][cout]
__device__ float g_W2T[128*CC];    // [cin][cout]
__device__ float g_q [BN*CC];      // point-major [bn][c]
__device__ float g_yk[BN*CC];
__device__ float g_yv[BN*CC];
__device__ float g_s1[BN*CC];      // x + attn_out (pre-BN1), point-major
__device__ float g_x1[BN*CC];      // BN1 output, point-major
__device__ float g_h [BN*128];     // lrelu(W1@x1), point-major
__device__ float g_s2[BN*CC];      // x1 + ff (pre-BN2), point-major
__device__ float g_ps[2][CC*16*2]; // stats partials: [which][(c*16+chunk)*2 + {sum,sq}]
__device__ float g_mean1[CC], g_rstd1[CC], g_mean2[CC], g_rstd2[CC];

// packed fp32x2 FMA (Blackwell FFMA2): d = a*b + c on both lanes
#define FMA_F32X2(d, a, b, c) \
    asm("fma.rn.f32x2 %0, %1, %2, %3;" : "=l"(d) : "l"(a), "l"(b), "l"(c))

// order-preserving float -> uint32 key
__device__ __forceinline__ unsigned fkey(float f) {
    unsigned b = __float_as_uint(f);
    return b ^ ((unsigned)((int)b >> 31) | 0x80000000u);
}

// 33-slot min-heap in smem, layout [pos][tid] with given stride; slot 32 = +inf
// sentinel. Early-exit sift-down insert replacing the root. Keys unique.
__device__ __forceinline__ void heap_insert(unsigned long long* hp, int tid,
                                            unsigned long long cur) {
    int p = 0;
#pragma unroll
    for (int l = 0; l < 5; l++) {
        int c1 = 2*p + 1;
        if (c1 > 31) break;
        unsigned long long k1 = hp[c1*128 + tid];
        unsigned long long k2 = hp[(c1+1)*128 + tid];
        bool lt = k1 < k2;
        unsigned long long ks = lt ? k1 : k2;
        int cs = lt ? c1 : c1 + 1;
        if (cur <= ks) break;
        hp[p*128 + tid] = ks;
        p = cs;
    }
    hp[p*128 + tid] = cur;
}

// ---------------- 0) transpose weights ----------------
__global__ void k_prep(const float* __restrict__ Wq, const float* __restrict__ Wk,
                       const float* __restrict__ Wv, const float* __restrict__ W1,
                       const float* __restrict__ W2) {
    int i = blockIdx.x * 256 + threadIdx.x;
    if (i < CC*CC) {
        int o = i >> 6, ci = i & 63;
        g_WT[0*CC*CC + ci*CC + o] = Wq[i];
        g_WT[1*CC*CC + ci*CC + o] = Wk[i];
        g_WT[2*CC*CC + ci*CC + o] = Wv[i];
    }
    if (i < 128*CC) {
        int o = i >> 6, ci = i & 63;      // W1[o][ci], o<128
        g_W1T[ci*128 + o] = W1[i];
        int co = i >> 7, k2 = i & 127;    // W2[co][k2], co<64
        g_W2T[k2*CC + co] = W2[i];
    }
}

// ---------------- 1) per-point squared norms ----------------
__global__ void k_xx(const float* __restrict__ x) {
    int b = blockIdx.y;
    int n = blockIdx.x * 256 + threadIdx.x;
    const float* xb = x + b*CC*NN;
    float s = 0.f;
#pragma unroll
    for (int c = 0; c < CC; c++) { float v = xb[c*NN + n]; s = fmaf(v, v, s); }
    g_xx[b*NN + n] = s;
}

// ---------------- 2) KNN pass 1: per-split top-32 ----------------
// 128 threads/block (thread = query), grid (NN/128, BB, NSPLIT).
#define HP(p) sh_heap[(p)*128 + tid]
#define CPAD 68

__global__ __launch_bounds__(128, 4) void k_knn(const float* __restrict__ x) {
    __shared__ __align__(16) float sh_c[32*CPAD];         // [m][c] candidate tile
    __shared__ float sh_xx[32];
    __shared__ unsigned long long sh_heap[33*128];        // 33.8KB

    int tid = threadIdx.x;
    int b   = blockIdx.y;
    int n   = blockIdx.x * 128 + tid;
    int cand0 = blockIdx.z * CPS;
    const float* xb = x + b*CC*NN;

    // query as packed channel pairs (q[2k], q[2k+1])
    unsigned long long qp[32];
#pragma unroll
    for (int k = 0; k < 32; k++) {
        float f0 = xb[(2*k  )*NN + n];
        float f1 = xb[(2*k+1)*NN + n];
        asm("mov.b64 %0, {%1, %2};" : "=l"(qp[k]) : "f"(f0), "f"(f1));
    }
    float xxn = g_xx[b*NN + n];

#pragma unroll
    for (int p = 0; p < 32; p++) HP(p) = 0ull;
    HP(32) = ~0ull;
    unsigned long long rootv = 0ull;

    for (int t = 0; t < CPS/32; t++) {
        int m0 = cand0 + t * 32;
        __syncthreads();
        for (int i = tid; i < 32*CC; i += 128) {
            int m = i & 31, c = i >> 5;
            sh_c[m*CPAD + c] = xb[c*NN + m0 + m];
        }
        if (tid < 32) sh_xx[tid] = g_xx[b*NN + m0 + tid];
        __syncthreads();

#pragma unroll 1
        for (int m4 = 0; m4 < 8; m4++) {
            unsigned long long acc[4] = {0ull, 0ull, 0ull, 0ull};
#pragma unroll
            for (int c4 = 0; c4 < 16; c4++) {
#pragma unroll
                for (int j = 0; j < 4; j++) {
                    ulonglong2 s = *(const ulonglong2*)&sh_c[(m4*4+j)*CPAD + c4*4];
                    FMA_F32X2(acc[j], qp[2*c4],   s.x, acc[j]);
                    FMA_F32X2(acc[j], qp[2*c4+1], s.y, acc[j]);
                }
            }
#pragma unroll
            for (int j = 0; j < 4; j++) {
                float lo, hi;
                asm("mov.b64 {%0, %1}, %2;" : "=f"(lo), "=f"(hi) : "l"(acc[j]));
                float a   = lo + hi;
                float val = fmaf(2.f, a, -xxn) - sh_xx[m4*4 + j];
                unsigned long long cur =
                    ((unsigned long long)fkey(val) << 32) | (unsigned)(m0 + m4*4 + j);
                if (cur > rootv) {
                    heap_insert(sh_heap, tid, cur);
                    rootv = HP(0);
                }
            }
        }
    }

    // transposed output: [entry][bn] -> coalesced stores and merge loads
    int bn = b*NN + n;
    unsigned long long* op = g_part + blockIdx.z*KK*BN + bn;
#pragma unroll
    for (int p = 0; p < KK; p++) op[p*BN] = HP(p);
}

// ---------------- 2b) KNN pass 2: merge 8x32 -> top-32 ----------------
// thread per query; streams 256 coalesced u64, same smem heap.
__global__ __launch_bounds__(128, 4) void k_mrg() {
    __shared__ unsigned long long sh_heap[33*128];
    int tid = threadIdx.x;
    int bn  = blockIdx.x * 128 + tid;

#pragma unroll
    for (int p = 0; p < 32; p++) HP(p) = 0ull;
    HP(32) = ~0ull;
    unsigned long long rootv = 0ull;

    const unsigned long long* src = g_part + bn;
#pragma unroll 1
    for (int j = 0; j < NSPLIT*KK; j += 8) {
        unsigned long long v[8];
#pragma unroll
        for (int u = 0; u < 8; u++) v[u] = src[(j+u)*BN];
#pragma unroll
        for (int u = 0; u < 8; u++) {
            if (v[u] > rootv) {
                heap_insert(sh_heap, tid, v[u]);
                rootv = HP(0);
            }
        }
    }

    int* op = g_idx + bn*KK;
#pragma unroll
    for (int i = 0; i < KK; i++) op[i] = (int)(unsigned)HP(i);
}

// ---------------- 3) projections q/yk/yv = W @ x (w = blockIdx.z) ----------------
__global__ void k_proj(const float* __restrict__ x) {
    __shared__ float shx[CC*64];   // [c][p]
    __shared__ float shW[CC*CC];   // [cin][cout]
    int b  = blockIdx.y;
    int w  = blockIdx.z;
    int n0 = blockIdx.x * 64;
    int tid = threadIdx.x;
    const float* xb = x + b*CC*NN;
    for (int i = tid; i < CC*64; i += 256) {
        int c = i >> 6, p = i & 63;
        shx[c*64 + p] = xb[c*NN + n0 + p];
    }
    for (int i = tid; i < CC*CC; i += 256) shW[i] = g_WT[w*CC*CC + i];
    __syncthreads();

    int p  = tid & 63;
    int cg = (tid >> 6) << 4;           // 16 output channels per thread
    int bn = b*NN + n0 + p;
    float4 acc[4];
#pragma unroll
    for (int g = 0; g < 4; g++) acc[g] = make_float4(0.f, 0.f, 0.f, 0.f);
#pragma unroll
    for (int k = 0; k < CC; k++) {
        float xv = shx[k*64 + p];
#pragma unroll
        for (int g = 0; g < 4; g++) {
            float4 wv = *(const float4*)&shW[k*CC + cg + g*4];
            acc[g].x = fmaf(xv, wv.x, acc[g].x);
            acc[g].y = fmaf(xv, wv.y, acc[g].y);
            acc[g].z = fmaf(xv, wv.z, acc[g].z);
            acc[g].w = fmaf(xv, wv.w, acc[g].w);
        }
    }
    float* dst = (w == 0 ? g_q : (w == 1 ? g_yk : g_yv)) + bn*CC + cg;
#pragma unroll
    for (int g = 0; g < 4; g++) *(float4*)&dst[g*4] = acc[g];
}

// ---------------- 4) attention (warp per point) + residual -> s1 ----------------
__global__ void k_attn(const float* __restrict__ x) {
    __shared__ float qsh[8][64];
    __shared__ float ykn[8][64];
    __shared__ float att[8][KK*8];
    __shared__ int   nid[8][KK];
    int tid  = threadIdx.x;
    int wid  = tid >> 5, lane = tid & 31;
    int bn   = blockIdx.x * 8 + wid;
    int b    = bn >> 11;
    int n    = bn & (NN - 1);

    qsh[wid][lane]      = g_q [bn*CC + lane];
    qsh[wid][lane + 32] = g_q [bn*CC + lane + 32];
    ykn[wid][lane]      = g_yk[bn*CC + lane];
    ykn[wid][lane + 32] = g_yk[bn*CC + lane + 32];
    int gn = b*NN + g_idx[bn*KK + lane];   // global row of this lane's neighbor
    nid[wid][lane] = gn;
    __syncwarp();

    const float4* kr = (const float4*)&g_yk[gn*CC];
    float e[8];
#pragma unroll
    for (int h = 0; h < 8; h++) e[h] = 0.f;
#pragma unroll
    for (int c4 = 0; c4 < 16; c4++) {
        float4 kv = kr[c4];
        int c = c4*4, h = c4 >> 1;
        float t = (kv.x - ykn[wid][c+0]) * qsh[wid][c+0];
        t = fmaf(kv.y - ykn[wid][c+1], qsh[wid][c+1], t);
        t = fmaf(kv.z - ykn[wid][c+2], qsh[wid][c+2], t);
        t = fmaf(kv.w - ykn[wid][c+3], qsh[wid][c+3], t);
        e[h] += t;
    }
    const float sc = 0.3535533905932738f;  // 1/sqrt(8)
#pragma unroll
    for (int h = 0; h < 8; h++) {
        float eh = e[h] * sc;
        float mx = eh;
#pragma unroll
        for (int o = 16; o > 0; o >>= 1) mx = fmaxf(mx, __shfl_xor_sync(0xffffffffu, mx, o));
        float ex = __expf(eh - mx);
        float sm = ex;
#pragma unroll
        for (int o = 16; o > 0; o >>= 1) sm += __shfl_xor_sync(0xffffffffu, sm, o);
        att[wid][lane*8 + h] = ex / sm;
    }
    __syncwarp();

    // out[c] = sum_j a[j][c>>3]*yv_j[c] - yv_center[c]  (softmax sums to 1)
    float acc0 = 0.f, acc1 = 0.f;
    int h0 = lane >> 3, h1 = (lane >> 3) + 4;
#pragma unroll 4
    for (int j = 0; j < KK; j++) {
        const float* vr = &g_yv[nid[wid][j]*CC];
        acc0 = fmaf(att[wid][j*8 + h0], vr[lane],      acc0);
        acc1 = fmaf(att[wid][j*8 + h1], vr[lane + 32], acc1);
    }
    acc0 -= g_yv[bn*CC + lane];
    acc1 -= g_yv[bn*CC + lane + 32];

    const float* xb = x + b*CC*NN;
    g_s1[bn*CC + lane]      = xb[lane*NN + n]        + acc0;
    g_s1[bn*CC + lane + 32] = xb[(lane + 32)*NN + n] + acc1;
}

// ---------------- 5a/8a) BN stats partials: grid (CC, 16) ----------------
__global__ void k_statsA(int which) {
    const float* s = which ? g_s2 : g_s1;
    int c = blockIdx.x, chunk = blockIdx.y, tid = threadIdx.x;
    int r0 = chunk * 1024;
    float sum = 0.f, sq = 0.f;
#pragma unroll
    for (int r = 0; r < 1024; r += 256) {
        float v = s[(r0 + r + tid)*CC + c];
        sum += v; sq = fmaf(v, v, sq);
    }
    __shared__ float ss[256], s2[256];
    ss[tid] = sum; s2[tid] = sq;
    __syncthreads();
    for (int st = 128; st > 0; st >>= 1) {
        if (tid < st) { ss[tid] += ss[tid + st]; s2[tid] += s2[tid + st]; }
        __syncthreads();
    }
    if (tid == 0) {
        g_ps[which][(c*16 + chunk)*2    ] = ss[0];
        g_ps[which][(c*16 + chunk)*2 + 1] = s2[0];
    }
}

// ---------------- 5b/8b) BN stats finalize: 1 block, 64 threads ----------------
__global__ void k_statsB(int which) {
    int c = threadIdx.x;
    float sum = 0.f, sq = 0.f;
#pragma unroll
    for (int k = 0; k < 16; k++) {
        sum += g_ps[which][(c*16 + k)*2];
        sq  += g_ps[which][(c*16 + k)*2 + 1];
    }
    float m   = sum * (1.f/BN);
    float var = sq  * (1.f/BN) - m*m;
    float r   = rsqrtf(var + 1e-5f);
    if (which) { g_mean2[c] = m; g_rstd2[c] = r; }
    else       { g_mean1[c] = m; g_rstd1[c] = r; }
}

// ---------------- 6) BN1 + h = lrelu(W1 @ x1); store x1, h ----------------
__global__ void k_ffn1(const float* __restrict__ gg1, const float* __restrict__ bb1) {
    __shared__ float x1sh[CC*32];   // [c][p], 8KB
    __shared__ float Wsh[CC*128];   // [cin][cout], 32KB
    int tid = threadIdx.x;
    int bn0 = blockIdx.x * 32;
    for (int i = tid; i < CC*128; i += 256) Wsh[i] = g_W1T[i];
    for (int i = tid; i < CC*32; i += 256) {
        int c = i >> 5, p = i & 31;
        float v = g_s1[(bn0 + p)*CC + c];
        float x1 = gg1[c]*(v - g_mean1[c])*g_rstd1[c] + bb1[c];
        x1sh[c*32 + p] = x1;
        g_x1[(bn0 + p)*CC + c] = x1;
    }
    __syncthreads();
    int p = tid & 31, og = (tid >> 5) * 16;
    float acc[16];
#pragma unroll
    for (int u = 0; u < 16; u++) acc[u] = 0.f;
#pragma unroll 8
    for (int k = 0; k < CC; k++) {
        float xv = x1sh[k*32 + p];
#pragma unroll
        for (int u = 0; u < 16; u++) acc[u] = fmaf(xv, Wsh[k*128 + og + u], acc[u]);
    }
    float* ho = g_h + (bn0 + p)*128 + og;
#pragma unroll
    for (int u4 = 0; u4 < 4; u4++) {
        float4 o;
        o.x = acc[u4*4+0] > 0.f ? acc[u4*4+0] : 0.2f*acc[u4*4+0];
        o.y = acc[u4*4+1] > 0.f ? acc[u4*4+1] : 0.2f*acc[u4*4+1];
        o.z = acc[u4*4+2] > 0.f ? acc[u4*4+2] : 0.2f*acc[u4*4+2];
        o.w = acc[u4*4+3] > 0.f ? acc[u4*4+3] : 0.2f*acc[u4*4+3];
        *(float4*)&ho[u4*4] = o;
    }
}

// ---------------- 7) s2 = x1 + W2 @ h ----------------
__global__ void k_ffn2() {
    __shared__ float hsh[128*16];   // [k][p], 8KB
    __shared__ float Wsh[128*CC];   // [k][cout], 32KB
    int tid = threadIdx.x;
    int bn0 = blockIdx.x * 16;
    for (int i = tid; i < 128*CC; i += 256) Wsh[i] = g_W2T[i];
    for (int i = tid; i < 128*16; i += 256) {
        int k = i >> 4, p = i & 15;
        hsh[k*16 + p] = g_h[(bn0 + p)*128 + k];
    }
    __syncthreads();
    int p = tid & 15, cg = (tid >> 4) * 4;
    float4 acc = make_float4(0.f, 0.f, 0.f, 0.f);
#pragma unroll 8
    for (int k = 0; k < 128; k++) {
        float hv = hsh[k*16 + p];
        float4 wv = *(const float4*)&Wsh[k*CC + cg];
        acc.x = fmaf(hv, wv.x, acc.x);
        acc.y = fmaf(hv, wv.y, acc.y);
        acc.z = fmaf(hv, wv.z, acc.z);
        acc.w = fmaf(hv, wv.w, acc.w);
    }
    int bn = bn0 + p;
    float4 x1v = *(const float4*)&g_x1[bn*CC + cg];
    float4 o;
    o.x = x1v.x + acc.x; o.y = x1v.y + acc.y;
    o.z = x1v.z + acc.z; o.w = x1v.w + acc.w;
    *(float4*)&g_s2[bn*CC + cg] = o;
}

// ---------------- 9) BN2 + transpose to (B, C, N) output ----------------
__global__ void k_final(const float* __restrict__ gg2, const float* __restrict__ bb2,
                        float* __restrict__ out) {
    int i = blockIdx.x * 256 + threadIdx.x;      // 0 .. B*C*N-1
    int n = i & (NN - 1);
    int c = (i >> 11) & 63;
    int b = i >> 17;
    float v = g_s2[(b*NN + n)*CC + c];
    out[i] = gg2[c]*(v - g_mean2[c])*g_rstd2[c] + bb2[c];
}

// ---------------- launcher ----------------
extern "C" void kernel_launch(void* const* d_in, const int* in_sizes, int n_in,
                              void* d_out, int out_size) {
    const float* x  = (const float*)d_in[0];
    const float* Wq = (const float*)d_in[1];
    const float* Wk = (const float*)d_in[2];
    const float* Wv = (const float*)d_in[3];
    const float* W1 = (const float*)d_in[4];
    const float* W2 = (const float*)d_in[5];
    const float* g1 = (const float*)d_in[6];
    const float* b1 = (const float*)d_in[7];
    const float* g2 = (const float*)d_in[8];
    const float* b2 = (const float*)d_in[9];
    float* out = (float*)d_out;

    k_prep  <<<32, 256>>>(Wq, Wk, Wv, W1, W2);
    k_xx    <<<dim3(NN/256, BB), 256>>>(x);
    k_knn   <<<dim3(NN/128, BB, NSPLIT), 128>>>(x);
    k_mrg   <<<BN/128, 128>>>();
    k_proj  <<<dim3(NN/64, BB, 3), 256>>>(x);
    k_attn  <<<BN/8, 256>>>(x);
    k_statsA<<<dim3(CC, 16), 256>>>(0);
    k_statsB<<<1, 64>>>(0);
    k_ffn1  <<<BN/32, 256>>>(g1, b1);
    k_ffn2  <<<BN/16, 256>>>();
    k_statsA<<<dim3(CC, 16), 256>>>(1);
    k_statsB<<<1, 64>>>(1);
    k_final <<<(BB*CC*NN)/256, 256>>>(g2, b2, out);
}

// round 9
// speedup vs baseline: 1.4598x; 1.0385x over previous
#include <cuda_runtime.h>
#include <math.h>

#define BB 8
#define CC 64
#define NN 2048
#define KK 32
#define BN (BB*NN)        // 16384 points
#define NSPLIT 4
#define CPS (NN/NSPLIT)   // 512 candidates per split

// ---------------- device scratch (no allocations allowed) ----------------
__device__ float g_xx[BN];
__device__ int   g_idx[BN*KK];
__device__ unsigned long long g_part[BN*NSPLIT*KK];   // [bn][split*32+p]
__device__ float g_WT [3*CC*CC];   // Wq/Wk/Wv transposed: [w][cin][cout]
__device__ float g_W1T[CC*128];    // [cin][cout]
__device__ float g_W2T[128*CC];    // [cin][cout]
__device__ float g_q [BN*CC];      // point-major [bn][c]
__device__ float g_yk[BN*CC];
__device__ float g_yv[BN*CC];
__device__ float g_s1[BN*CC];      // x + attn_out (pre-BN1), point-major
__device__ float g_x1[BN*CC];      // BN1 output, point-major
__device__ float g_h [BN*128];     // lrelu(W1@x1), point-major
__device__ float g_s2[BN*CC];      // x1 + ff (pre-BN2), point-major
__device__ float g_ps[2][CC*16*2]; // stats partials
__device__ float g_mean1[CC], g_rstd1[CC], g_mean2[CC], g_rstd2[CC];

// packed fp32x2 FMA (Blackwell FFMA2): d = a*b + c on both lanes
#define FMA_F32X2(d, a, b, c) \
    asm("fma.rn.f32x2 %0, %1, %2, %3;" : "=l"(d) : "l"(a), "l"(b), "l"(c))

// order-preserving float -> uint32 key
__device__ __forceinline__ unsigned fkey(float f) {
    unsigned b = __float_as_uint(f);
    return b ^ ((unsigned)((int)b >> 31) | 0x80000000u);
}

// 33-slot min-heap in smem, layout [pos][tid]; slot 32 = +inf sentinel.
// Early-exit sift-down insert replacing the root. Keys unique.
__device__ __forceinline__ void heap_insert(unsigned long long* hp, int tid,
                                            unsigned long long cur) {
    int p = 0;
#pragma unroll
    for (int l = 0; l < 5; l++) {
        int c1 = 2*p + 1;
        if (c1 > 31) break;
        unsigned long long k1 = hp[c1*128 + tid];
        unsigned long long k2 = hp[(c1+1)*128 + tid];
        bool lt = k1 < k2;
        unsigned long long ks = lt ? k1 : k2;
        int cs = lt ? c1 : c1 + 1;
        if (cur <= ks) break;
        hp[p*128 + tid] = ks;
        p = cs;
    }
    hp[p*128 + tid] = cur;
}

// ---------------- 0) transpose weights ----------------
__global__ void k_prep(const float* __restrict__ Wq, const float* __restrict__ Wk,
                       const float* __restrict__ Wv, const float* __restrict__ W1,
                       const float* __restrict__ W2) {
    int i = blockIdx.x * 256 + threadIdx.x;
    if (i < CC*CC) {
        int o = i >> 6, ci = i & 63;
        g_WT[0*CC*CC + ci*CC + o] = Wq[i];
        g_WT[1*CC*CC + ci*CC + o] = Wk[i];
        g_WT[2*CC*CC + ci*CC + o] = Wv[i];
    }
    if (i < 128*CC) {
        int o = i >> 6, ci = i & 63;      // W1[o][ci], o<128
        g_W1T[ci*128 + o] = W1[i];
        int co = i >> 7, k2 = i & 127;    // W2[co][k2], co<64
        g_W2T[k2*CC + co] = W2[i];
    }
}

// ---------------- 1) per-point squared norms ----------------
__global__ void k_xx(const float* __restrict__ x) {
    int b = blockIdx.y;
    int n = blockIdx.x * 256 + threadIdx.x;
    const float* xb = x + b*CC*NN;
    float s = 0.f;
#pragma unroll
    for (int c = 0; c < CC; c++) { float v = xb[c*NN + n]; s = fmaf(v, v, s); }
    g_xx[b*NN + n] = s;
}

// ---------------- 2) KNN pass 1: per-split top-32 ----------------
// 128 threads/block (thread = query), grid (NN/128, BB, NSPLIT).
#define HP(p) sh_heap[(p)*128 + tid]
#define CPAD 68

__global__ __launch_bounds__(128, 4) void k_knn(const float* __restrict__ x) {
    __shared__ __align__(16) float sh_c[32*CPAD];         // [m][c] candidate tile
    __shared__ float sh_xx[32];
    __shared__ unsigned long long sh_heap[33*128];        // 33.8KB

    int tid = threadIdx.x;
    int b   = blockIdx.y;
    int n   = blockIdx.x * 128 + tid;
    int cand0 = blockIdx.z * CPS;
    const float* xb = x + b*CC*NN;

    // query as packed channel pairs (q[2k], q[2k+1])
    unsigned long long qp[32];
#pragma unroll
    for (int k = 0; k < 32; k++) {
        float f0 = xb[(2*k  )*NN + n];
        float f1 = xb[(2*k+1)*NN + n];
        asm("mov.b64 %0, {%1, %2};" : "=l"(qp[k]) : "f"(f0), "f"(f1));
    }
    float xxn = g_xx[b*NN + n];

#pragma unroll
    for (int p = 0; p < 32; p++) HP(p) = 0ull;
    HP(32) = ~0ull;
    unsigned long long rootv = 0ull;

    for (int t = 0; t < CPS/32; t++) {
        int m0 = cand0 + t * 32;
        __syncthreads();
        for (int i = tid; i < 32*CC; i += 128) {
            int m = i & 31, c = i >> 5;
            sh_c[m*CPAD + c] = xb[c*NN + m0 + m];
        }
        if (tid < 32) sh_xx[tid] = g_xx[b*NN + m0 + tid];
        __syncthreads();

#pragma unroll 1
        for (int m4 = 0; m4 < 8; m4++) {
            unsigned long long acc[4] = {0ull, 0ull, 0ull, 0ull};
#pragma unroll
            for (int c4 = 0; c4 < 16; c4++) {
#pragma unroll
                for (int j = 0; j < 4; j++) {
                    ulonglong2 s = *(const ulonglong2*)&sh_c[(m4*4+j)*CPAD + c4*4];
                    FMA_F32X2(acc[j], qp[2*c4],   s.x, acc[j]);
                    FMA_F32X2(acc[j], qp[2*c4+1], s.y, acc[j]);
                }
            }
#pragma unroll
            for (int j = 0; j < 4; j++) {
                float lo, hi;
                asm("mov.b64 {%0, %1}, %2;" : "=f"(lo), "=f"(hi) : "l"(acc[j]));
                float a   = lo + hi;
                float val = fmaf(2.f, a, -xxn) - sh_xx[m4*4 + j];
                unsigned long long cur =
                    ((unsigned long long)fkey(val) << 32) | (unsigned)(m0 + m4*4 + j);
                if (cur > rootv) {
                    heap_insert(sh_heap, tid, cur);
                    rootv = HP(0);
                }
            }
        }
    }

    int bn = b*NN + n;
    unsigned long long* op = g_part + bn*(NSPLIT*KK) + blockIdx.z*KK;
#pragma unroll
    for (int p = 0; p < KK; p++) op[p] = HP(p);
}

// ---------------- 2b) KNN pass 2: merge 4x32 -> top-32 ----------------
// warp per query, register-resident: lane sorts its 4 entries descending,
// then 32 extract-max rounds (lane head O(1), warp max via shfl). Keys unique.
#define CE(a, b) { if (a < b) { unsigned long long _t = a; a = b; b = _t; } }

__global__ void k_mrg() {
    int tid  = threadIdx.x;
    int wid  = tid >> 5, lane = tid & 31;
    int bn   = blockIdx.x * 8 + wid;
    const unsigned long long* src = g_part + bn*(NSPLIT*KK);

    unsigned long long v0 = src[lane], v1 = src[lane+32],
                       v2 = src[lane+64], v3 = src[lane+96];
    // sort descending: v0 >= v1 >= v2 >= v3
    CE(v0, v1); CE(v2, v3); CE(v0, v2); CE(v1, v3); CE(v1, v2);

    unsigned long long head = v0;
    int ptr = 0;
    int* op = g_idx + bn*KK;
#pragma unroll 1
    for (int i = 0; i < KK; i++) {
        unsigned long long wm = head;
#pragma unroll
        for (int o = 16; o > 0; o >>= 1) {
            unsigned long long t = __shfl_xor_sync(0xffffffffu, wm, o);
            wm = t > wm ? t : wm;
        }
        if (head == wm) {   // unique owner
            ptr++;
            head = (ptr == 1) ? v1 : (ptr == 2) ? v2 : (ptr == 3) ? v3 : 0ull;
        }
        if (lane == i) op[i] = (int)(unsigned)wm;
    }
}

// ---------------- 3) projections q/yk/yv = W @ x (w = blockIdx.z) ----------------
__global__ void k_proj(const float* __restrict__ x) {
    __shared__ float shx[CC*64];   // [c][p]
    __shared__ float shW[CC*CC];   // [cin][cout]
    int b  = blockIdx.y;
    int w  = blockIdx.z;
    int n0 = blockIdx.x * 64;
    int tid = threadIdx.x;
    const float* xb = x + b*CC*NN;
    for (int i = tid; i < CC*64; i += 256) {
        int c = i >> 6, p = i & 63;
        shx[c*64 + p] = xb[c*NN + n0 + p];
    }
    for (int i = tid; i < CC*CC; i += 256) shW[i] = g_WT[w*CC*CC + i];
    __syncthreads();

    int p  = tid & 63;
    int cg = (tid >> 6) << 4;           // 16 output channels per thread
    int bn = b*NN + n0 + p;
    float4 acc[4];
#pragma unroll
    for (int g = 0; g < 4; g++) acc[g] = make_float4(0.f, 0.f, 0.f, 0.f);
#pragma unroll
    for (int k = 0; k < CC; k++) {
        float xv = shx[k*64 + p];
#pragma unroll
        for (int g = 0; g < 4; g++) {
            float4 wv = *(const float4*)&shW[k*CC + cg + g*4];
            acc[g].x = fmaf(xv, wv.x, acc[g].x);
            acc[g].y = fmaf(xv, wv.y, acc[g].y);
            acc[g].z = fmaf(xv, wv.z, acc[g].z);
            acc[g].w = fmaf(xv, wv.w, acc[g].w);
        }
    }
    float* dst = (w == 0 ? g_q : (w == 1 ? g_yk : g_yv)) + bn*CC + cg;
#pragma unroll
    for (int g = 0; g < 4; g++) *(float4*)&dst[g*4] = acc[g];
}

// ---------------- 4) attention (warp per point) + residual -> s1 ----------------
__global__ void k_attn(const float* __restrict__ x) {
    __shared__ float qsh[8][64];
    __shared__ float ykn[8][64];
    __shared__ float att[8][KK*8];
    __shared__ int   nid[8][KK];
    int tid  = threadIdx.x;
    int wid  = tid >> 5, lane = tid & 31;
    int bn   = blockIdx.x * 8 + wid;
    int b    = bn >> 11;
    int n    = bn & (NN - 1);

    qsh[wid][lane]      = g_q [bn*CC + lane];
    qsh[wid][lane + 32] = g_q [bn*CC + lane + 32];
    ykn[wid][lane]      = g_yk[bn*CC + lane];
    ykn[wid][lane + 32] = g_yk[bn*CC + lane + 32];
    int gn = b*NN + g_idx[bn*KK + lane];   // global row of this lane's neighbor
    nid[wid][lane] = gn;
    __syncwarp();

    const float4* kr = (const float4*)&g_yk[gn*CC];
    float e[8];
#pragma unroll
    for (int h = 0; h < 8; h++) e[h] = 0.f;
#pragma unroll
    for (int c4 = 0; c4 < 16; c4++) {
        float4 kv = kr[c4];
        int c = c4*4, h = c4 >> 1;
        float t = (kv.x - ykn[wid][c+0]) * qsh[wid][c+0];
        t = fmaf(kv.y - ykn[wid][c+1], qsh[wid][c+1], t);
        t = fmaf(kv.z - ykn[wid][c+2], qsh[wid][c+2], t);
        t = fmaf(kv.w - ykn[wid][c+3], qsh[wid][c+3], t);
        e[h] += t;
    }
    const float sc = 0.3535533905932738f;  // 1/sqrt(8)
#pragma unroll
    for (int h = 0; h < 8; h++) {
        float eh = e[h] * sc;
        float mx = eh;
#pragma unroll
        for (int o = 16; o > 0; o >>= 1) mx = fmaxf(mx, __shfl_xor_sync(0xffffffffu, mx, o));
        float ex = __expf(eh - mx);
        float sm = ex;
#pragma unroll
        for (int o = 16; o > 0; o >>= 1) sm += __shfl_xor_sync(0xffffffffu, sm, o);
        att[wid][lane*8 + h] = ex / sm;
    }
    __syncwarp();

    // out[c] = sum_j a[j][c>>3]*yv_j[c] - yv_center[c]  (softmax sums to 1)
    float acc0 = 0.f, acc1 = 0.f;
    int h0 = lane >> 3, h1 = (lane >> 3) + 4;
#pragma unroll 4
    for (int j = 0; j < KK; j++) {
        const float* vr = &g_yv[nid[wid][j]*CC];
        acc0 = fmaf(att[wid][j*8 + h0], vr[lane],      acc0);
        acc1 = fmaf(att[wid][j*8 + h1], vr[lane + 32], acc1);
    }
    acc0 -= g_yv[bn*CC + lane];
    acc1 -= g_yv[bn*CC + lane + 32];

    const float* xb = x + b*CC*NN;
    g_s1[bn*CC + lane]      = xb[lane*NN + n]        + acc0;
    g_s1[bn*CC + lane + 32] = xb[(lane + 32)*NN + n] + acc1;
}

// ---------------- 5a/8a) BN stats partials: grid (CC, 16) ----------------
__global__ void k_statsA(int which) {
    const float* s = which ? g_s2 : g_s1;
    int c = blockIdx.x, chunk = blockIdx.y, tid = threadIdx.x;
    int r0 = chunk * 1024;
    float sum = 0.f, sq = 0.f;
#pragma unroll
    for (int r = 0; r < 1024; r += 256) {
        float v = s[(r0 + r + tid)*CC + c];
        sum += v; sq = fmaf(v, v, sq);
    }
    __shared__ float ss[256], s2[256];
    ss[tid] = sum; s2[tid] = sq;
    __syncthreads();
    for (int st = 128; st > 0; st >>= 1) {
        if (tid < st) { ss[tid] += ss[tid + st]; s2[tid] += s2[tid + st]; }
        __syncthreads();
    }
    if (tid == 0) {
        g_ps[which][(c*16 + chunk)*2    ] = ss[0];
        g_ps[which][(c*16 + chunk)*2 + 1] = s2[0];
    }
}

// ---------------- 5b/8b) BN stats finalize ----------------
__global__ void k_statsB(int which) {
    int c = threadIdx.x;
    float sum = 0.f, sq = 0.f;
#pragma unroll
    for (int k = 0; k < 16; k++) {
        sum += g_ps[which][(c*16 + k)*2];
        sq  += g_ps[which][(c*16 + k)*2 + 1];
    }
    float m   = sum * (1.f/BN);
    float var = sq  * (1.f/BN) - m*m;
    float r   = rsqrtf(var + 1e-5f);
    if (which) { g_mean2[c] = m; g_rstd2[c] = r; }
    else       { g_mean1[c] = m; g_rstd1[c] = r; }
}

// ---------------- 6) BN1 + h = lrelu(W1 @ x1); store x1, h ----------------
__global__ void k_ffn1(const float* __restrict__ gg1, const float* __restrict__ bb1) {
    __shared__ float x1sh[CC*32];   // [c][p], 8KB
    __shared__ float Wsh[CC*128];   // [cin][cout], 32KB
    int tid = threadIdx.x;
    int bn0 = blockIdx.x * 32;
    for (int i = tid; i < CC*128; i += 256) Wsh[i] = g_W1T[i];
    for (int i = tid; i < CC*32; i += 256) {
        int c = i >> 5, p = i & 31;
        float v = g_s1[(bn0 + p)*CC + c];
        float x1 = gg1[c]*(v - g_mean1[c])*g_rstd1[c] + bb1[c];
        x1sh[c*32 + p] = x1;
        g_x1[(bn0 + p)*CC + c] = x1;
    }
    __syncthreads();
    int p = tid & 31, og = (tid >> 5) * 16;
    float acc[16];
#pragma unroll
    for (int u = 0; u < 16; u++) acc[u] = 0.f;
#pragma unroll 8
    for (int k = 0; k < CC; k++) {
        float xv = x1sh[k*32 + p];
#pragma unroll
        for (int u = 0; u < 16; u++) acc[u] = fmaf(xv, Wsh[k*128 + og + u], acc[u]);
    }
    float* ho = g_h + (bn0 + p)*128 + og;
#pragma unroll
    for (int u4 = 0; u4 < 4; u4++) {
        float4 o;
        o.x = acc[u4*4+0] > 0.f ? acc[u4*4+0] : 0.2f*acc[u4*4+0];
        o.y = acc[u4*4+1] > 0.f ? acc[u4*4+1] : 0.2f*acc[u4*4+1];
        o.z = acc[u4*4+2] > 0.f ? acc[u4*4+2] : 0.2f*acc[u4*4+2];
        o.w = acc[u4*4+3] > 0.f ? acc[u4*4+3] : 0.2f*acc[u4*4+3];
        *(float4*)&ho[u4*4] = o;
    }
}

// ---------------- 7) s2 = x1 + W2 @ h ----------------
__global__ void k_ffn2() {
    __shared__ float hsh[128*16];   // [k][p], 8KB
    __shared__ float Wsh[128*CC];   // [k][cout], 32KB
    int tid = threadIdx.x;
    int bn0 = blockIdx.x * 16;
    for (int i = tid; i < 128*CC; i += 256) Wsh[i] = g_W2T[i];
    for (int i = tid; i < 128*16; i += 256) {
        int k = i >> 4, p = i & 15;
        hsh[k*16 + p] = g_h[(bn0 + p)*128 + k];
    }
    __syncthreads();
    int p = tid & 15, cg = (tid >> 4) * 4;
    float4 acc = make_float4(0.f, 0.f, 0.f, 0.f);
#pragma unroll 8
    for (int k = 0; k < 128; k++) {
        float hv = hsh[k*16 + p];
        float4 wv = *(const float4*)&Wsh[k*CC + cg];
        acc.x = fmaf(hv, wv.x, acc.x);
        acc.y = fmaf(hv, wv.y, acc.y);
        acc.z = fmaf(hv, wv.z, acc.z);
        acc.w = fmaf(hv, wv.w, acc.w);
    }
    int bn = bn0 + p;
    float4 x1v = *(const float4*)&g_x1[bn*CC + cg];
    float4 o;
    o.x = x1v.x + acc.x; o.y = x1v.y + acc.y;
    o.z = x1v.z + acc.z; o.w = x1v.w + acc.w;
    *(float4*)&g_s2[bn*CC + cg] = o;
}

// ---------------- 9) BN2 + transpose to (B, C, N) output ----------------
__global__ void k_final(const float* __restrict__ gg2, const float* __restrict__ bb2,
                        float* __restrict__ out) {
    int i = blockIdx.x * 256 + threadIdx.x;      // 0 .. B*C*N-1
    int n = i & (NN - 1);
    int c = (i >> 11) & 63;
    int b = i >> 17;
    float v = g_s2[(b*NN + n)*CC + c];
    out[i] = gg2[c]*(v - g_mean2[c])*g_rstd2[c] + bb2[c];
}

// ---------------- launcher ----------------
extern "C" void kernel_launch(void* const* d_in, const int* in_sizes, int n_in,
                              void* d_out, int out_size) {
    const float* x  = (const float*)d_in[0];
    const float* Wq = (const float*)d_in[1];
    const float* Wk = (const float*)d_in[2];
    const float* Wv = (const float*)d_in[3];
    const float* W1 = (const float*)d_in[4];
    const float* W2 = (const float*)d_in[5];
    const float* g1 = (const float*)d_in[6];
    const float* b1 = (const float*)d_in[7];
    const float* g2 = (const float*)d_in[8];
    const float* b2 = (const float*)d_in[9];
    float* out = (float*)d_out;

    k_prep  <<<32, 256>>>(Wq, Wk, Wv, W1, W2);
    k_xx    <<<dim3(NN/256, BB), 256>>>(x);
    k_knn   <<<dim3(NN/128, BB, NSPLIT), 128>>>(x);
    k_mrg   <<<BN/8, 256>>>();
    k_proj  <<<dim3(NN/64, BB, 3), 256>>>(x);
    k_attn  <<<BN/8, 256>>>(x);
    k_statsA<<<dim3(CC, 16), 256>>>(0);
    k_statsB<<<1, 64>>>(0);
    k_ffn1  <<<BN/32, 256>>>(g1, b1);
    k_ffn2  <<<BN/16, 256>>>();
    k_statsA<<<dim3(CC, 16), 256>>>(1);
    k_statsB<<<1, 64>>>(1);
    k_final <<<(BB*CC*NN)/256, 256>>>(g2, b2, out);
}